// round 5
// baseline (speedup 1.0000x reference)
#include <cuda_runtime.h>

// Problem constants
#define BATCH    32
#define CH       2048
#define SZ       4096
#define CSPLIT   16                 // c-dimension splits
#define CCHUNK   (CH / CSPLIT)      // 128 c iterations per block
#define BG       4                  // batches per block (w reuse factor)
#define TPB      128                // threads per block
#define S_PER_BLOCK (TPB * 4)       // 512 s-columns per block (float4/thread)
#define NGROUPS  ((SZ / S_PER_BLOCK) * (BATCH / BG))   // 64 reduction groups

// 16 * 32 * 4096 floats = 8 MB partial-sum scratch (L2-resident between store & reduce)
__device__ float g_partial[CSPLIT * BATCH * SZ];
// per-group arrival counters; zero-initialized, reset by the last block each run
__device__ unsigned int g_count[NGROUPS];

// Streaming load (evict-first): 1 GiB of x must not thrash w / partials out of L2
__device__ __forceinline__ float4 ldcs4(const float* p) {
    float4 v;
    asm volatile("ld.global.cs.v4.f32 {%0,%1,%2,%3}, [%4];"
                 : "=f"(v.x), "=f"(v.y), "=f"(v.z), "=f"(v.w) : "l"(p));
    return v;
}

// L2-scope load (bypass L1): read other CTAs' partials at the coherence point
__device__ __forceinline__ float4 ldcg4(const float* p) {
    float4 v;
    asm volatile("ld.global.cg.v4.f32 {%0,%1,%2,%3}, [%4];"
                 : "=f"(v.x), "=f"(v.y), "=f"(v.z), "=f"(v.w) : "l"(p));
    return v;
}

__global__ __launch_bounds__(TPB) void CWG_fused_kernel(
    const float* __restrict__ x,
    const float* __restrict__ w,
    const float* __restrict__ bias,
    float* __restrict__ out)
{
    const int s0  = blockIdx.x * S_PER_BLOCK + threadIdx.x * 4;
    const int b0  = blockIdx.y * BG;
    const int cs  = blockIdx.z;
    const int c0  = cs * CCHUNK;
    const int grp = blockIdx.y * (SZ / S_PER_BLOCK) + blockIdx.x;

    float4 acc[BG];
#pragma unroll
    for (int b = 0; b < BG; b++) acc[b] = make_float4(0.f, 0.f, 0.f, 0.f);

    const float* wp = w + (size_t)c0 * SZ + s0;
    const float* xp = x + ((size_t)b0 * CH + (size_t)c0) * SZ + s0;

#pragma unroll 4
    for (int c = 0; c < CCHUNK; c++) {
        const float4 wv = __ldg((const float4*)(wp + (size_t)c * SZ));
#pragma unroll
        for (int b = 0; b < BG; b++) {
            const float4 xv = ldcs4(xp + ((size_t)b * CH + (size_t)c) * SZ);
            acc[b].x = fmaf(xv.x, wv.x, acc[b].x);
            acc[b].y = fmaf(xv.y, wv.y, acc[b].y);
            acc[b].z = fmaf(xv.z, wv.z, acc[b].z);
            acc[b].w = fmaf(xv.w, wv.w, acc[b].w);
        }
    }

    // Store partials with DEFAULT policy (stay L2-resident for the reducer)
#pragma unroll
    for (int b = 0; b < BG; b++) {
        *(float4*)(g_partial + ((size_t)cs * BATCH + (size_t)(b0 + b)) * SZ + s0) = acc[b];
    }

    // ---- last-CTA-in-group reduction handshake (threadFenceReduction pattern) ----
    // 1. each thread fences ITS OWN partial stores to device scope
    __threadfence();
    // 2. barrier: guarantees ALL threads' fences precede thread0's arrival tick
    //    (this ordering was missing in R3/R4 and caused the races)
    __syncthreads();
    __shared__ unsigned int s_last;
    if (threadIdx.x == 0)
        s_last = atomicAdd(&g_count[grp], 1u);
    __syncthreads();
    if (s_last != CSPLIT - 1) return;       // not the last arrival

    // 3. acquire side: order our partial reads after the observed arrivals
    __threadfence();

    const float4 bv = *(const float4*)(bias + (s0 & (SZ - 1)));

#pragma unroll
    for (int b = 0; b < BG; b++) {
        float4 sum = make_float4(0.f, 0.f, 0.f, 0.f);
        const float* base = g_partial + (size_t)(b0 + b) * SZ + s0;
#pragma unroll
        for (int k = 0; k < CSPLIT; k++) {
            // fixed k-order summation => bitwise deterministic regardless of
            // which block arrives last; use own registers at k == cs
            if (k == cs) {
                sum.x += acc[b].x; sum.y += acc[b].y;
                sum.z += acc[b].z; sum.w += acc[b].w;
            } else {
                const float4 p = ldcg4(base + (size_t)k * BATCH * SZ);
                sum.x += p.x; sum.y += p.y; sum.z += p.z; sum.w += p.w;
            }
        }
        float4 r;
        r.x = fmaxf(sum.x + bv.x, 0.f);
        r.y = fmaxf(sum.y + bv.y, 0.f);
        r.z = fmaxf(sum.z + bv.z, 0.f);
        r.w = fmaxf(sum.w + bv.w, 0.f);
        *(float4*)(out + (size_t)(b0 + b) * SZ + s0) = r;
    }

    // reset counter so the next graph replay starts from a clean state
    if (threadIdx.x == 0)
        g_count[grp] = 0u;
}

extern "C" void kernel_launch(void* const* d_in, const int* in_sizes, int n_in,
                              void* d_out, int out_size)
{
    const float* x    = (const float*)d_in[0];
    const float* w    = (const float*)d_in[1];
    const float* bias = (const float*)d_in[2];
    float* out        = (float*)d_out;

    dim3 grid(SZ / S_PER_BLOCK, BATCH / BG, CSPLIT);  // (8, 8, 16) = 1024 blocks
    CWG_fused_kernel<<<grid, TPB>>>(x, w, bias, out);
}

// round 6
// speedup vs baseline: 1.0343x; 1.0343x over previous
#include <cuda_runtime.h>

// Problem constants
#define BATCH    32
#define CH       2048
#define SZ       4096
#define CSPLIT   16                 // c-dimension splits
#define CCHUNK   (CH / CSPLIT)      // 128 c iterations per block
#define BG       4                  // batches per block (w reuse factor)
#define TPB      128                // threads per block
#define S_PER_BLOCK (TPB * 4)       // 512 s-columns per block (float4/thread)

// 16 * 32 * 4096 floats = 8 MB partial-sum scratch.
// Stored with DEFAULT policy -> stays L2-resident for the finalize kernel.
__device__ float g_partial[CSPLIT * BATCH * SZ];

// Streaming load (evict-first): 1 GiB of x must not thrash w/partials out of L2
__device__ __forceinline__ float4 ldcs4(const float* p) {
    float4 v;
    asm volatile("ld.global.cs.v4.f32 {%0,%1,%2,%3}, [%4];"
                 : "=f"(v.x), "=f"(v.y), "=f"(v.z), "=f"(v.w) : "l"(p));
    return v;
}

// L2-scope load: partials are L2-hot; skip L1
__device__ __forceinline__ float4 ldcg4(const float* p) {
    float4 v;
    asm volatile("ld.global.cg.v4.f32 {%0,%1,%2,%3}, [%4];"
                 : "=f"(v.x), "=f"(v.y), "=f"(v.z), "=f"(v.w) : "l"(p));
    return v;
}

__global__ __launch_bounds__(TPB) void CWG_partial_kernel(
    const float* __restrict__ x,
    const float* __restrict__ w)
{
    const int s0  = blockIdx.x * S_PER_BLOCK + threadIdx.x * 4;
    const int b0  = blockIdx.y * BG;
    const int cs  = blockIdx.z;
    const int c0  = cs * CCHUNK;

    float4 acc[BG];
#pragma unroll
    for (int b = 0; b < BG; b++) acc[b] = make_float4(0.f, 0.f, 0.f, 0.f);

    const float* wp = w + (size_t)c0 * SZ + s0;
    const float* xp = x + ((size_t)b0 * CH + (size_t)c0) * SZ + s0;

#pragma unroll 4
    for (int c = 0; c < CCHUNK; c++) {
        const float4 wv = __ldg((const float4*)(wp + (size_t)c * SZ));
#pragma unroll
        for (int b = 0; b < BG; b++) {
            const float4 xv = ldcs4(xp + ((size_t)b * CH + (size_t)c) * SZ);
            acc[b].x = fmaf(xv.x, wv.x, acc[b].x);
            acc[b].y = fmaf(xv.y, wv.y, acc[b].y);
            acc[b].z = fmaf(xv.z, wv.z, acc[b].z);
            acc[b].w = fmaf(xv.w, wv.w, acc[b].w);
        }
    }

    // DEFAULT-policy stores: keep the 8 MB of partials L2-resident so the
    // finalize kernel reads them at L2 bandwidth (R2's .cs stores forced them
    // to DRAM and made finalize 6.4us instead of ~2us).
#pragma unroll
    for (int b = 0; b < BG; b++) {
        *(float4*)(g_partial + ((size_t)cs * BATCH + (size_t)(b0 + b)) * SZ + s0) = acc[b];
    }
}

__global__ __launch_bounds__(128) void CWG_finalize_kernel(
    const float* __restrict__ bias,
    float* __restrict__ out)
{
    // 256 blocks x 128 threads = 32768 threads, one float4 output each.
    const int i4 = blockIdx.x * 128 + threadIdx.x;   // float4 index
    const int i  = i4 * 4;                           // over BATCH*SZ = 131072
    const int s  = i & (SZ - 1);

    // 16 independent L2 loads per thread (full MLP, latency overlapped)
    float4 sum = make_float4(0.f, 0.f, 0.f, 0.f);
#pragma unroll
    for (int k = 0; k < CSPLIT; k++) {
        const float4 p = ldcg4(g_partial + (size_t)k * BATCH * SZ + i);
        sum.x += p.x; sum.y += p.y; sum.z += p.z; sum.w += p.w;
    }

    const float4 bv = *(const float4*)(bias + s);
    float4 r;
    r.x = fmaxf(sum.x + bv.x, 0.f);
    r.y = fmaxf(sum.y + bv.y, 0.f);
    r.z = fmaxf(sum.z + bv.z, 0.f);
    r.w = fmaxf(sum.w + bv.w, 0.f);
    *(float4*)(out + i) = r;
}

extern "C" void kernel_launch(void* const* d_in, const int* in_sizes, int n_in,
                              void* d_out, int out_size)
{
    const float* x    = (const float*)d_in[0];
    const float* w    = (const float*)d_in[1];
    const float* bias = (const float*)d_in[2];
    float* out        = (float*)d_out;

    dim3 grid(SZ / S_PER_BLOCK, BATCH / BG, CSPLIT);  // (8, 8, 16) = 1024 blocks
    CWG_partial_kernel<<<grid, TPB>>>(x, w);

    CWG_finalize_kernel<<<(BATCH * SZ / 4) / 128, 128>>>(bias, out);
}